// round 15
// baseline (speedup 1.0000x reference)
#include <cuda_runtime.h>
#include <cstdint>

#define TT 256
#define BB 512
#define DD 256
#define HH 256
#define G32 32

__device__ float g_xw[(size_t)BB * TT * G32];
__device__ float g_wfold[8 * G32];
__device__ float g_bfold[G32];

__device__ __forceinline__ float fsigmoid(float x) {
    return __fdividef(1.0f, 1.0f + __expf(-x));
}
__device__ __forceinline__ float ftanh(float x) {
    return __fdividef(2.0f, 1.0f + __expf(-2.0f * x)) - 1.0f;
}

__global__ void prep_kernel(const float* __restrict__ Wproj,
                            const float* __restrict__ Wab,
                            const float* __restrict__ bab) {
    int q = threadIdx.x >> 5;
    int k = threadIdx.x & 31;
    float acc = 0.f;
    for (int h = 0; h < HH; h++)
        acc += Wab[q * HH + h] * Wproj[(DD + h) * G32 + k];
    g_wfold[q * G32 + k] = acc;
    if (threadIdx.x < 32) {
        float bacc = 0.f;
        for (int h = 0; h < HH; h++)
            bacc += bab[h] * Wproj[(DD + h) * G32 + threadIdx.x];
        g_bfold[threadIdx.x] = bacc;
    }
}

// (T,B,D) @ W_proj[:D] -> g_xw[b][t][k].  grid=(B/64, T), 256 thr.
__global__ void __launch_bounds__(256) xproj_kernel(const float* __restrict__ x,
                                                    const float* __restrict__ Wproj,
                                                    const float* __restrict__ bproj) {
    __shared__ float Wsm[DD * G32];
    int t  = blockIdx.y;
    int b0 = blockIdx.x * 64;
    for (int u = threadIdx.x; u < DD * G32; u += 256) Wsm[u] = Wproj[u];
    __syncthreads();

    int k  = threadIdx.x & 31;
    int g8 = threadIdx.x >> 5;
    int b  = b0 + g8 * 8;

    float acc[8];
    float bp = bproj[k];
#pragma unroll
    for (int r = 0; r < 8; r++) acc[r] = bp;

    const float* xb = x + ((size_t)t * BB + b) * DD;
    for (int j4 = 0; j4 < DD; j4 += 4) {
        float xa[8][4];
#pragma unroll
        for (int r = 0; r < 8; r++) {
            float4 v = *(const float4*)(xb + (size_t)r * DD + j4);
            xa[r][0] = v.x; xa[r][1] = v.y; xa[r][2] = v.z; xa[r][3] = v.w;
        }
#pragma unroll
        for (int jj = 0; jj < 4; jj++) {
            float wv = Wsm[(j4 + jj) * G32 + k];
#pragma unroll
            for (int r = 0; r < 8; r++) acc[r] += xa[r][jj] * wv;
        }
    }
#pragma unroll
    for (int r = 0; r < 8; r++)
        g_xw[((size_t)(b + r) * TT + t) * G32 + k] = acc[r];
}

// one CTA per batch row; 256 threads = one per hidden unit; 256 steps in-kernel
__global__ void __launch_bounds__(256, 4) recur_kernel(
    const float* __restrict__ Wqp,  const float* __restrict__ bqp,
    const float* __restrict__ thg,  const float* __restrict__ tha,
    const float* __restrict__ Wap,  const float* __restrict__ bap,
    const float* __restrict__ Wab,  const float* __restrict__ bab,
    float* __restrict__ out) {

    __shared__ float s_e[32];
    __shared__ float s_hmid[HH];
    __shared__ float s_part[8][9];
    __shared__ float s_hq[8];
    __shared__ float s_wfold[8][32];
    __shared__ float s_bfold[32];
    __shared__ float s_thg4[32];
    __shared__ float s_tha[8];
    __shared__ float s_bap[8];
    __shared__ float s_wapT[8][HH + 1];

    const int tid = threadIdx.x;
    const int b   = blockIdx.x;

    float wqp[8], wab[8];
#pragma unroll
    for (int q = 0; q < 8; q++) {
        wqp[q] = Wqp[q * HH + tid];
        wab[q] = Wab[q * HH + tid];
    }
    float bq = bqp[tid], ba = bab[tid];

    if (tid < 32) { s_thg4[tid] = thg[tid & 7]; s_bfold[tid] = g_bfold[tid]; }
    if (tid < 8)  { s_tha[tid] = tha[tid]; s_bap[tid] = bap[tid]; }
    for (int u = tid; u < 8 * 32; u += 256) s_wfold[u >> 5][u & 31] = g_wfold[u];
    for (int u = tid; u < 8 * HH; u += 256) {
        int i = u >> 8, h = u & 255;
        s_wapT[i][h] = Wap[h * 8 + i];
    }

    float cx = 0.f;
    const float* xwb = g_xw + (size_t)b * TT * G32;
    float xwreg = (tid < 32) ? xwb[tid] : 0.f;
    __syncthreads();

    for (int t = 0; t < TT; t++) {
        // gate preactivations (32) + qgate -> s_e   (warp 0)
        if (tid < 32) {
            float g = xwreg;
            if (t > 0) {
                g += s_bfold[tid];
#pragma unroll
                for (int q = 0; q < 8; q++) g += s_hq[q] * s_wfold[q][tid];
            }
            if (t + 1 < TT) xwreg = xwb[(size_t)(t + 1) * G32 + tid];

            float c = __cosf(g + s_thg4[tid]);
            int q = tid & 7;
            float pre = c, suf = c;
#pragma unroll
            for (int d = 1; d < 8; d <<= 1) {
                float u1 = __shfl_up_sync(0xFFFFFFFFu, pre, d, 8);
                if (q >= d) pre *= u1;
                float u2 = __shfl_down_sync(0xFFFFFFFFu, suf, d, 8);
                if (q + d < 8) suf *= u2;
            }
            float suf1 = __shfl_sync(0xFFFFFFFFu, suf, (tid & 24) + 1, 32);
            s_e[tid] = (q == 0) ? suf1 : pre;
        }
        __syncthreads();

        // qgate outputs @ W_qproj + b ; activations ; LSTM cell   (all 256)
        float pf = bq, pi = bq, pg = bq, po = bq;
#pragma unroll
        for (int q = 0; q < 8; q++) {
            float w = wqp[q];
            pf += s_e[q]      * w;
            pi += s_e[8 + q]  * w;
            pg += s_e[16 + q] * w;
            po += s_e[24 + q] * w;
        }
        float f  = fsigmoid(pf);
        float ig = fsigmoid(pi);
        float gg = ftanh(pg);
        float o  = fsigmoid(po);
        cx = f * cx + ig * gg;
        float hmid = o * ftanh(cx);
        s_hmid[tid] = hmid;
        __syncthreads();

        // hmid(256) @ W_attn_proj(256,8) partials
        if (tid < 64) {
            int i8 = tid & 7, c8 = tid >> 3;
            const float* hm = &s_hmid[c8 * 32];
            const float* wt = &s_wapT[i8][c8 * 32];
            float acc = 0.f;
#pragma unroll
            for (int m = 0; m < 32; m++) acc += hm[m] * wt[m];
            s_part[c8][i8] = acc;
        }
        __syncthreads();

        // reduce + attention qgate -> s_hq  (8 lanes)
        if (tid < 8) {
            float a = s_bap[tid];
#pragma unroll
            for (int c = 0; c < 8; c++) a += s_part[c][tid];
            float cc = __cosf(a + s_tha[tid]);
            float pre = cc, suf = cc;
#pragma unroll
            for (int d = 1; d < 8; d <<= 1) {
                float u1 = __shfl_up_sync(0xFFu, pre, d, 8);
                if (tid >= d) pre *= u1;
                float u2 = __shfl_down_sync(0xFFu, suf, d, 8);
                if (tid + d < 8) suf *= u2;
            }
            float suf1 = __shfl_sync(0xFFu, suf, 1, 8);
            s_hq[tid] = (tid == 0) ? suf1 : pre;
        }
        __syncthreads();

        // hx = hq @ W_attn_back + b_ab
        float hx = ba;
#pragma unroll
        for (int q = 0; q < 8; q++) hx += s_hq[q] * wab[q];
        out[((size_t)t * BB + b) * HH + tid] = hx;

        if (t == TT - 1) {
            out[(size_t)TT * BB * HH + (size_t)b * HH + tid] = hx;
            out[(size_t)TT * BB * HH + (size_t)BB * HH + (size_t)b * HH + tid] = cx;
        }
    }
}

extern "C" void kernel_launch(void* const* d_in, const int* in_sizes, int n_in,
                              void* d_out, int out_size) {
    const float* inputs = (const float*)d_in[0];
    const float* Wproj  = (const float*)d_in[1];
    const float* bproj  = (const float*)d_in[2];
    const float* thg    = (const float*)d_in[3];
    const float* Wqp    = (const float*)d_in[4];
    const float* bqp    = (const float*)d_in[5];
    const float* tha    = (const float*)d_in[6];
    const float* Wap    = (const float*)d_in[7];
    const float* bap    = (const float*)d_in[8];
    const float* Wab    = (const float*)d_in[9];
    const float* bab    = (const float*)d_in[10];
    float* out = (float*)d_out;

    prep_kernel<<<1, 256>>>(Wproj, Wab, bab);
    dim3 gx(BB / 64, TT);
    xproj_kernel<<<gx, 256>>>(inputs, Wproj, bproj);
    recur_kernel<<<BB, 256>>>(Wqp, bqp, thg, tha, Wap, bap, Wab, bab, out);
}